// round 4
// baseline (speedup 1.0000x reference)
#include <cuda_runtime.h>

// MPJRDLayer fused forward — flat massive-TLP version.
// x:     [B=128, N=1024, D=8, S=64] fp32 (512 contiguous floats per (b,n))
// W:     [1024, 512] fp32;  theta, r_hat: [1024]
// out:   spikes [B*N] ++ rates [N] ++ thetas [N] ++ r_hats [N]

#define NB   128
#define NN   1024
#define DS   512

// Kernel 1: one warp computes spikes for (n, b0) and (n, b0+1).
// 65536 warps total = 8192 blocks x 8 warps.
__global__ __launch_bounds__(256)
void mpjrd_spikes_kernel(const float* __restrict__ x,
                         const float* __restrict__ W,
                         const float* __restrict__ theta,
                         float* __restrict__ out)
{
    const int warp = threadIdx.x >> 5;
    const int lane = threadIdx.x & 31;
    const int id   = blockIdx.x * 8 + warp;      // 0 .. 65535
    const int n    = id & (NN - 1);
    const int b0   = (id >> 10) << 1;            // 0,2,...,126
    const int b1   = b0 + 1;

    // W row (L2-resident after first wave: 2 MB total)
    const float4* Wv = reinterpret_cast<const float4*>(W + (size_t)n * DS);
    const float4 w0 = Wv[0 * 32 + lane];
    const float4 w1 = Wv[1 * 32 + lane];
    const float4 w2 = Wv[2 * 32 + lane];
    const float4 w3 = Wv[3 * 32 + lane];

    const float4* xa = reinterpret_cast<const float4*>(x + ((size_t)b0 * NN + n) * DS);
    const float4* xb = reinterpret_cast<const float4*>(x + ((size_t)b1 * NN + n) * DS);

    const float4 a0 = xa[0 * 32 + lane];
    const float4 a1 = xa[1 * 32 + lane];
    const float4 a2 = xa[2 * 32 + lane];
    const float4 a3 = xa[3 * 32 + lane];
    const float4 c0 = xb[0 * 32 + lane];
    const float4 c1 = xb[1 * 32 + lane];
    const float4 c2 = xb[2 * 32 + lane];
    const float4 c3 = xb[3 * 32 + lane];

    float accA = 0.0f, accB = 0.0f;
    accA = fmaf(a0.x, w0.x, accA); accA = fmaf(a0.y, w0.y, accA);
    accA = fmaf(a0.z, w0.z, accA); accA = fmaf(a0.w, w0.w, accA);
    accA = fmaf(a1.x, w1.x, accA); accA = fmaf(a1.y, w1.y, accA);
    accA = fmaf(a1.z, w1.z, accA); accA = fmaf(a1.w, w1.w, accA);
    accA = fmaf(a2.x, w2.x, accA); accA = fmaf(a2.y, w2.y, accA);
    accA = fmaf(a2.z, w2.z, accA); accA = fmaf(a2.w, w2.w, accA);
    accA = fmaf(a3.x, w3.x, accA); accA = fmaf(a3.y, w3.y, accA);
    accA = fmaf(a3.z, w3.z, accA); accA = fmaf(a3.w, w3.w, accA);

    accB = fmaf(c0.x, w0.x, accB); accB = fmaf(c0.y, w0.y, accB);
    accB = fmaf(c0.z, w0.z, accB); accB = fmaf(c0.w, w0.w, accB);
    accB = fmaf(c1.x, w1.x, accB); accB = fmaf(c1.y, w1.y, accB);
    accB = fmaf(c1.z, w1.z, accB); accB = fmaf(c1.w, w1.w, accB);
    accB = fmaf(c2.x, w2.x, accB); accB = fmaf(c2.y, w2.y, accB);
    accB = fmaf(c2.z, w2.z, accB); accB = fmaf(c2.w, w2.w, accB);
    accB = fmaf(c3.x, w3.x, accB); accB = fmaf(c3.y, w3.y, accB);
    accB = fmaf(c3.z, w3.z, accB); accB = fmaf(c3.w, w3.w, accB);

    #pragma unroll
    for (int off = 16; off; off >>= 1) {
        accA += __shfl_xor_sync(0xFFFFFFFFu, accA, off);
        accB += __shfl_xor_sync(0xFFFFFFFFu, accB, off);
    }

    if (lane == 0) {
        const float th = theta[n];
        out[(size_t)b0 * NN + n] = (accA >= th) ? 1.0f : 0.0f;
        out[(size_t)b1 * NN + n] = (accB >= th) ? 1.0f : 0.0f;
    }
}

// Kernel 2: per-neuron reduction over b + homeostatic update.
// 8 blocks x 128 threads; thread handles one n.
__global__ __launch_bounds__(128)
void mpjrd_rates_kernel(const float* __restrict__ theta,
                        const float* __restrict__ r_hat,
                        float* __restrict__ out)
{
    const int n = blockIdx.x * 128 + threadIdx.x;

    const float* sp = out + n;
    float c = 0.0f;
    #pragma unroll 8
    for (int b = 0; b < NB; ++b)
        c += sp[(size_t)b * NN];

    const float rate = c * (1.0f / 128.0f);
    const float rh   = 0.95f * r_hat[n] + 0.05f * rate;
    const float thn  = theta[n] + 0.1f * (rh - 0.1f);
    out[NB * NN + n]          = rate;
    out[NB * NN + NN + n]     = thn;
    out[NB * NN + 2 * NN + n] = rh;
}

extern "C" void kernel_launch(void* const* d_in, const int* in_sizes, int n_in,
                              void* d_out, int out_size)
{
    const float* x     = (const float*)d_in[0];
    const float* W     = (const float*)d_in[1];
    const float* theta = (const float*)d_in[2];
    const float* r_hat = (const float*)d_in[3];
    float* out = (float*)d_out;

    mpjrd_spikes_kernel<<<8192, 256>>>(x, W, theta, out);
    mpjrd_rates_kernel<<<8, 128>>>(theta, r_hat, out);
}

// round 8
// speedup vs baseline: 1.0456x; 1.0456x over previous
#include <cuda_runtime.h>

// MPJRDLayer fused forward — flat massive-TLP + last-block finalize.
// x:     [B=128, N=1024, D=8, S=64] fp32 (512 contiguous floats per (b,n))
// W:     [1024, 512] fp32;  theta, r_hat: [1024]
// out:   spikes [B*N] ++ rates [N] ++ thetas [N] ++ r_hats [N]

#define NB   128
#define NN   1024
#define DS   512
#define GRID 8192

__device__ float        g_cnt[NN];   // zero-initialized; reset by last block
__device__ unsigned int g_done;      // zero-initialized; reset by last block

__global__ __launch_bounds__(256)
void mpjrd_fused_kernel(const float* __restrict__ x,
                        const float* __restrict__ W,
                        const float* __restrict__ theta,
                        const float* __restrict__ r_hat,
                        float* __restrict__ out)
{
    __shared__ bool is_last;

    const int warp = threadIdx.x >> 5;
    const int lane = threadIdx.x & 31;
    const int id   = blockIdx.x * 8 + warp;      // 0 .. 65535
    const int n    = id & (NN - 1);
    const int b0   = (id >> 10) << 1;            // 0,2,...,126
    const int b1   = b0 + 1;

    // Hoist theta so it batches with the other front loads (lane 0 needs it)
    const float th = __ldg(theta + n);

    // W row (L2-resident after first wave: 2 MB total)
    const float4* Wv = reinterpret_cast<const float4*>(W + (size_t)n * DS);
    const float4 w0 = Wv[0 * 32 + lane];
    const float4 w1 = Wv[1 * 32 + lane];
    const float4 w2 = Wv[2 * 32 + lane];
    const float4 w3 = Wv[3 * 32 + lane];

    const float4* xa = reinterpret_cast<const float4*>(x + ((size_t)b0 * NN + n) * DS);
    const float4* xb = reinterpret_cast<const float4*>(x + ((size_t)b1 * NN + n) * DS);

    const float4 a0 = xa[0 * 32 + lane];
    const float4 a1 = xa[1 * 32 + lane];
    const float4 a2 = xa[2 * 32 + lane];
    const float4 a3 = xa[3 * 32 + lane];
    const float4 c0 = xb[0 * 32 + lane];
    const float4 c1 = xb[1 * 32 + lane];
    const float4 c2 = xb[2 * 32 + lane];
    const float4 c3 = xb[3 * 32 + lane];

    float accA = 0.0f, accB = 0.0f;
    accA = fmaf(a0.x, w0.x, accA); accA = fmaf(a0.y, w0.y, accA);
    accA = fmaf(a0.z, w0.z, accA); accA = fmaf(a0.w, w0.w, accA);
    accA = fmaf(a1.x, w1.x, accA); accA = fmaf(a1.y, w1.y, accA);
    accA = fmaf(a1.z, w1.z, accA); accA = fmaf(a1.w, w1.w, accA);
    accA = fmaf(a2.x, w2.x, accA); accA = fmaf(a2.y, w2.y, accA);
    accA = fmaf(a2.z, w2.z, accA); accA = fmaf(a2.w, w2.w, accA);
    accA = fmaf(a3.x, w3.x, accA); accA = fmaf(a3.y, w3.y, accA);
    accA = fmaf(a3.z, w3.z, accA); accA = fmaf(a3.w, w3.w, accA);

    accB = fmaf(c0.x, w0.x, accB); accB = fmaf(c0.y, w0.y, accB);
    accB = fmaf(c0.z, w0.z, accB); accB = fmaf(c0.w, w0.w, accB);
    accB = fmaf(c1.x, w1.x, accB); accB = fmaf(c1.y, w1.y, accB);
    accB = fmaf(c1.z, w1.z, accB); accB = fmaf(c1.w, w1.w, accB);
    accB = fmaf(c2.x, w2.x, accB); accB = fmaf(c2.y, w2.y, accB);
    accB = fmaf(c2.z, w2.z, accB); accB = fmaf(c2.w, w2.w, accB);
    accB = fmaf(c3.x, w3.x, accB); accB = fmaf(c3.y, w3.y, accB);
    accB = fmaf(c3.z, w3.z, accB); accB = fmaf(c3.w, w3.w, accB);

    #pragma unroll
    for (int off = 16; off; off >>= 1) {
        accA += __shfl_xor_sync(0xFFFFFFFFu, accA, off);
        accB += __shfl_xor_sync(0xFFFFFFFFu, accB, off);
    }

    if (lane == 0) {
        const float sA = (accA >= th) ? 1.0f : 0.0f;
        const float sB = (accB >= th) ? 1.0f : 0.0f;
        out[(size_t)b0 * NN + n] = sA;
        out[(size_t)b1 * NN + n] = sB;
        const float s = sA + sB;
        if (s != 0.0f) atomicAdd(&g_cnt[n], s);   // order-invariant (integer sums)
    }

    // ── Retirement: last block computes the per-neuron homeostatic update ──
    __syncthreads();
    if (threadIdx.x == 0) {
        __threadfence();                                   // publish g_cnt adds
        const unsigned int v = atomicAdd(&g_done, 1u);
        is_last = (v == (unsigned int)(GRID - 1));
    }
    __syncthreads();

    if (is_last) {
        __threadfence();                                   // acquire all g_cnt
        for (int i = threadIdx.x; i < NN; i += 256) {
            const float c = g_cnt[i];
            g_cnt[i] = 0.0f;                               // reset for next replay
            const float rate = c * (1.0f / 128.0f);
            const float rh   = 0.95f * __ldg(r_hat + i) + 0.05f * rate;
            const float thn  = __ldg(theta + i) + 0.1f * (rh - 0.1f);
            out[NB * NN + i]          = rate;
            out[NB * NN + NN + i]     = thn;
            out[NB * NN + 2 * NN + i] = rh;
        }
        if (threadIdx.x == 0) g_done = 0u;                 // reset for next replay
    }
}

extern "C" void kernel_launch(void* const* d_in, const int* in_sizes, int n_in,
                              void* d_out, int out_size)
{
    const float* x     = (const float*)d_in[0];
    const float* W     = (const float*)d_in[1];
    const float* theta = (const float*)d_in[2];
    const float* r_hat = (const float*)d_in[3];
    float* out = (float*)d_out;

    mpjrd_fused_kernel<<<GRID, 256>>>(x, W, theta, r_hat, out);
}

// round 9
// speedup vs baseline: 1.0885x; 1.0410x over previous
#include <cuda_runtime.h>

// MPJRDLayer fused forward — two-kernel: flat massive-TLP spikes + parallel rates.
// x:     [B=128, N=1024, D=8, S=64] fp32 (512 contiguous floats per (b,n))
// W:     [1024, 512] fp32;  theta, r_hat: [1024]
// out:   spikes [B*N] ++ rates [N] ++ thetas [N] ++ r_hats [N]

#define NB   128
#define NN   1024
#define DS   512

// ── Kernel 1: one warp computes spikes for (n, b0) and (n, b0+1). ──
// 65536 warps = 8192 blocks x 8 warps.  (Unchanged from R3: measured ~39.5us.)
__global__ __launch_bounds__(256)
void mpjrd_spikes_kernel(const float* __restrict__ x,
                         const float* __restrict__ W,
                         const float* __restrict__ theta,
                         float* __restrict__ out)
{
    const int warp = threadIdx.x >> 5;
    const int lane = threadIdx.x & 31;
    const int id   = blockIdx.x * 8 + warp;      // 0 .. 65535
    const int n    = id & (NN - 1);
    const int b0   = (id >> 10) << 1;            // 0,2,...,126
    const int b1   = b0 + 1;

    const float4* Wv = reinterpret_cast<const float4*>(W + (size_t)n * DS);
    const float4 w0 = Wv[0 * 32 + lane];
    const float4 w1 = Wv[1 * 32 + lane];
    const float4 w2 = Wv[2 * 32 + lane];
    const float4 w3 = Wv[3 * 32 + lane];

    const float4* xa = reinterpret_cast<const float4*>(x + ((size_t)b0 * NN + n) * DS);
    const float4* xb = reinterpret_cast<const float4*>(x + ((size_t)b1 * NN + n) * DS);

    const float4 a0 = xa[0 * 32 + lane];
    const float4 a1 = xa[1 * 32 + lane];
    const float4 a2 = xa[2 * 32 + lane];
    const float4 a3 = xa[3 * 32 + lane];
    const float4 c0 = xb[0 * 32 + lane];
    const float4 c1 = xb[1 * 32 + lane];
    const float4 c2 = xb[2 * 32 + lane];
    const float4 c3 = xb[3 * 32 + lane];

    float accA = 0.0f, accB = 0.0f;
    accA = fmaf(a0.x, w0.x, accA); accA = fmaf(a0.y, w0.y, accA);
    accA = fmaf(a0.z, w0.z, accA); accA = fmaf(a0.w, w0.w, accA);
    accA = fmaf(a1.x, w1.x, accA); accA = fmaf(a1.y, w1.y, accA);
    accA = fmaf(a1.z, w1.z, accA); accA = fmaf(a1.w, w1.w, accA);
    accA = fmaf(a2.x, w2.x, accA); accA = fmaf(a2.y, w2.y, accA);
    accA = fmaf(a2.z, w2.z, accA); accA = fmaf(a2.w, w2.w, accA);
    accA = fmaf(a3.x, w3.x, accA); accA = fmaf(a3.y, w3.y, accA);
    accA = fmaf(a3.z, w3.z, accA); accA = fmaf(a3.w, w3.w, accA);

    accB = fmaf(c0.x, w0.x, accB); accB = fmaf(c0.y, w0.y, accB);
    accB = fmaf(c0.z, w0.z, accB); accB = fmaf(c0.w, w0.w, accB);
    accB = fmaf(c1.x, w1.x, accB); accB = fmaf(c1.y, w1.y, accB);
    accB = fmaf(c1.z, w1.z, accB); accB = fmaf(c1.w, w1.w, accB);
    accB = fmaf(c2.x, w2.x, accB); accB = fmaf(c2.y, w2.y, accB);
    accB = fmaf(c2.z, w2.z, accB); accB = fmaf(c2.w, w2.w, accB);
    accB = fmaf(c3.x, w3.x, accB); accB = fmaf(c3.y, w3.y, accB);
    accB = fmaf(c3.z, w3.z, accB); accB = fmaf(c3.w, w3.w, accB);

    #pragma unroll
    for (int off = 16; off; off >>= 1) {
        accA += __shfl_xor_sync(0xFFFFFFFFu, accA, off);
        accB += __shfl_xor_sync(0xFFFFFFFFu, accB, off);
    }

    if (lane == 0) {
        const float th = theta[n];
        out[(size_t)b0 * NN + n] = (accA >= th) ? 1.0f : 0.0f;
        out[(size_t)b1 * NN + n] = (accB >= th) ? 1.0f : 0.0f;
    }
}

// ── Kernel 2: parallel column-sum of spikes + homeostatic update. ──
// 8 blocks x 256 threads. Block g owns neurons [128g, 128g+128).
// Warp w owns b-chunk [16w, 16w+16); lanes give coalesced n-contiguous loads.
__global__ __launch_bounds__(256)
void mpjrd_rates_kernel(const float* __restrict__ theta,
                        const float* __restrict__ r_hat,
                        float* __restrict__ out)
{
    __shared__ float part[8][128];   // [warp][local neuron]

    const int warp = threadIdx.x >> 5;
    const int lane = threadIdx.x & 31;
    const int nbase = blockIdx.x * 128;

    #pragma unroll
    for (int nn = 0; nn < 4; ++nn) {
        const int n = nbase + nn * 32 + lane;
        const float* sp = out + n + (size_t)(warp * 16) * NN;
        float acc = 0.0f;
        #pragma unroll
        for (int i = 0; i < 16; ++i)
            acc += sp[(size_t)i * NN];
        part[warp][nn * 32 + lane] = acc;
    }
    __syncthreads();

    if (threadIdx.x < 128) {
        const int t = threadIdx.x;
        float c = 0.0f;
        #pragma unroll
        for (int w = 0; w < 8; ++w) c += part[w][t];

        const int n = nbase + t;
        const float rate = c * (1.0f / 128.0f);
        const float rh   = 0.95f * __ldg(r_hat + n) + 0.05f * rate;
        const float thn  = __ldg(theta + n) + 0.1f * (rh - 0.1f);
        out[NB * NN + n]          = rate;
        out[NB * NN + NN + n]     = thn;
        out[NB * NN + 2 * NN + n] = rh;
    }
}

extern "C" void kernel_launch(void* const* d_in, const int* in_sizes, int n_in,
                              void* d_out, int out_size)
{
    const float* x     = (const float*)d_in[0];
    const float* W     = (const float*)d_in[1];
    const float* theta = (const float*)d_in[2];
    const float* r_hat = (const float*)d_in[3];
    float* out = (float*)d_out;

    mpjrd_spikes_kernel<<<8192, 256>>>(x, W, theta, out);
    mpjrd_rates_kernel<<<8, 256>>>(theta, r_hat, out);
}